// round 1
// baseline (speedup 1.0000x reference)
#include <cuda_runtime.h>
#include <math.h>

#define N_NODES 50000
#define E_EDGES 800000
#define H 128
#define EF 16
#define DIM 3
#define MF 276

#define TILE_E 128
#define LDF 284      // padded row stride of f tile (bank-friendly: 284 % 32 == 28)
#define KLOOP1 280   // k-loop bound for MF GEMMs (276 rounded up to 8)
#define LDS1 132     // row stride of stage buffer
#define TILE_N 128
#define LDF2 260     // node-feature row stride (K=256 real)

// Scratch accumulators (no cudaMalloc allowed)
__device__ float g_hagg[N_NODES * H];
__device__ float g_xagg[N_NODES * DIM];

// -------------------------------------------------------------------------
// Shared-memory tiled GEMM: C[128 x 128] = sA[128 x K] * gW[K x 128]
// 256 threads, each computes an 8x8 micro-tile. W staged 8 rows at a time.
// -------------------------------------------------------------------------
__device__ __forceinline__ void gemm128(const float* __restrict__ sA, int lda,
                                        const float* __restrict__ gW,
                                        int Kreal, int Kloop,
                                        float* sW, float acc[8][8])
{
    const int tid = threadIdx.x;
    const int tx = tid & 15;
    const int ty = tid >> 4;

#pragma unroll
    for (int i = 0; i < 8; ++i)
#pragma unroll
        for (int j = 0; j < 8; ++j) acc[i][j] = 0.f;

    for (int k0 = 0; k0 < Kloop; k0 += 8) {
        // stage W[k0..k0+8) x 128 into shared (each thread one float4)
        const int wr = tid >> 5;           // 0..7
        const int wc = (tid & 31) << 2;    // 0..124
        float4 wv = make_float4(0.f, 0.f, 0.f, 0.f);
        if (k0 + wr < Kreal)
            wv = *(const float4*)(gW + (size_t)(k0 + wr) * H + wc);
        __syncthreads();   // previous chunk fully consumed
        *(float4*)(sW + wr * H + wc) = wv;
        __syncthreads();   // chunk visible

#pragma unroll
        for (int kk = 0; kk < 8; ++kk) {
            float a[8];
#pragma unroll
            for (int i = 0; i < 8; ++i)
                a[i] = sA[(ty * 8 + i) * lda + k0 + kk];
            float4 b0 = *(const float4*)(sW + kk * H + tx * 8);
            float4 b1 = *(const float4*)(sW + kk * H + tx * 8 + 4);
            float b[8] = {b0.x, b0.y, b0.z, b0.w, b1.x, b1.y, b1.z, b1.w};
#pragma unroll
            for (int i = 0; i < 8; ++i)
#pragma unroll
                for (int j = 0; j < 8; ++j)
                    acc[i][j] = fmaf(a[i], b[j], acc[i][j]);
        }
    }
    __syncthreads();       // all reads done before caller overwrites buffers
}

__device__ __forceinline__ float silu(float v) {
    return v / (1.f + __expf(-v));
}

// bias + SiLU, store to stage buffer
__device__ __forceinline__ void silu_store(float acc[8][8],
                                           const float* __restrict__ bias,
                                           float* __restrict__ s1)
{
    const int tid = threadIdx.x;
    const int tx = tid & 15;
    const int ty = tid >> 4;
#pragma unroll
    for (int j = 0; j < 8; ++j) {
        const float bb = bias[tx * 8 + j];
#pragma unroll
        for (int i = 0; i < 8; ++i) {
            float v = acc[i][j] + bb;
            s1[(ty * 8 + i) * LDS1 + tx * 8 + j] = silu(v);
        }
    }
}

// -------------------------------------------------------------------------
// Edge kernel: one CTA = 128 edges
// -------------------------------------------------------------------------
#define EDGE_SMEM ((TILE_E*LDF + TILE_E*LDS1 + 1024 + TILE_E*4 + TILE_E*3 + TILE_E*2) * 4)

__global__ void __launch_bounds__(256, 1)
edge_kernel(const float* __restrict__ h, const float* __restrict__ coords,
            const float* __restrict__ a,
            const int* __restrict__ src, const int* __restrict__ dst,
            const float* __restrict__ We1, const float* __restrict__ be1,
            const float* __restrict__ We2, const float* __restrict__ be2,
            const float* __restrict__ Wa,  const float* __restrict__ ba,
            const float* __restrict__ Wc1, const float* __restrict__ bc1,
            const float* __restrict__ Wc2, const float* __restrict__ bc2,
            const float* __restrict__ Wc3)
{
    extern __shared__ float sm[];
    float* sf    = sm;                        // 128 x 284
    float* s1    = sf + TILE_E * LDF;         // 128 x 132
    float* sW    = s1 + TILE_E * LDS1;        // 8 x 128
    float* sdiff = sW + 1024;                 // 128 x 4 (dx,dy,dz,r)
    float* satt  = sdiff + TILE_E * 4;        // 128
    float* sWa   = satt + TILE_E;             // 128
    float* sWc3  = sWa + TILE_E;              // 128
    int*   ssrc  = (int*)(sWc3 + TILE_E);     // 128
    int*   sdst  = ssrc + TILE_E;             // 128

    const int tid = threadIdx.x;
    const int e0  = blockIdx.x * TILE_E;

    // per-edge scalars + D section + zero-pad
    if (tid < TILE_E) {
        const int e = e0 + tid;
        const int s = src[e], d = dst[e];
        ssrc[tid] = s; sdst[tid] = d;
        float dx = coords[s * 3 + 0] - coords[d * 3 + 0];
        float dy = coords[s * 3 + 1] - coords[d * 3 + 1];
        float dz = coords[s * 3 + 2] - coords[d * 3 + 2];
        float r  = sqrtf(dx * dx + dy * dy + dz * dz);
        sdiff[tid * 4 + 0] = dx;
        sdiff[tid * 4 + 1] = dy;
        sdiff[tid * 4 + 2] = dz;
        sdiff[tid * 4 + 3] = r;
        float* frow = sf + tid * LDF;
        frow[256] = r;
        frow[257] = fabsf(dx);
        frow[258] = fabsf(dy);
        frow[259] = fabsf(dz);
#pragma unroll
        for (int c = 276; c < LDF; ++c) frow[c] = 0.f;
        sWa[tid]  = Wa[tid];
        sWc3[tid] = Wc3[tid];
    }
    __syncthreads();

    // gather h[src], h[dst] (float4), L2-resident table
    for (int idx = tid; idx < TILE_E * 64; idx += 256) {
        const int e = idx >> 6, c = idx & 63;
        const int node = (c < 32) ? ssrc[e] : sdst[e];
        const float4 v = ((const float4*)h)[(size_t)node * 32 + (c & 31)];
        ((float4*)(sf + e * LDF))[c] = v;
    }
    // gather a
    for (int idx = tid; idx < TILE_E * 4; idx += 256) {
        const int e = idx >> 2, c = idx & 3;
        ((float4*)(sf + e * LDF + 260))[c] = ((const float4*)a)[(size_t)(e0 + e) * 4 + c];
    }
    // (first sync inside gemm128 makes gathers visible)

    float acc[8][8];

    // ---- edge MLP ----
    gemm128(sf, LDF, We1, MF, KLOOP1, sW, acc);
    silu_store(acc, be1, s1);
    gemm128(s1, LDS1, We2, H, H, sW, acc);
    silu_store(acc, be2, s1);
    __syncthreads();

    // attention gate: att[e] = sigmoid(mh[e] . Wa + ba)
    if (tid < TILE_E) {
        float s = 0.f;
        const float* row = s1 + tid * LDS1;
#pragma unroll 8
        for (int c = 0; c < H; ++c) s = fmaf(row[c], sWa[c], s);
        s += ba[0];
        satt[tid] = 1.f / (1.f + __expf(-s));
    }
    __syncthreads();

    // scatter msg_h = att * mh into g_hagg[dst]
    for (int idx = tid; idx < TILE_E * H; idx += 256) {
        const int e = idx >> 7, c = idx & 127;
        const float v = satt[e] * s1[e * LDS1 + c];
        atomicAdd(&g_hagg[(size_t)sdst[e] * H + c], v);
    }

    // ---- coord MLP ----
    gemm128(sf, LDF, Wc1, MF, KLOOP1, sW, acc);
    silu_store(acc, bc1, s1);
    gemm128(s1, LDS1, Wc2, H, H, sW, acc);
    silu_store(acc, bc2, s1);
    __syncthreads();

    // cm3 + scatter msg_x
    if (tid < TILE_E) {
        float s = 0.f;
        const float* row = s1 + tid * LDS1;
#pragma unroll 8
        for (int c = 0; c < H; ++c) s = fmaf(row[c], sWc3[c], s);
        const float dx = sdiff[tid * 4 + 0];
        const float dy = sdiff[tid * 4 + 1];
        const float dz = sdiff[tid * 4 + 2];
        const float r  = sdiff[tid * 4 + 3];
        const float g  = s / (r + 1.f);
        const int d = sdst[tid];
        atomicAdd(&g_xagg[d * 3 + 0], g * dx);
        atomicAdd(&g_xagg[d * 3 + 1], g * dy);
        atomicAdd(&g_xagg[d * 3 + 2], g * dz);
    }
}

// -------------------------------------------------------------------------
// Node kernel: one CTA = 128 nodes
// -------------------------------------------------------------------------
#define NODE_SMEM ((TILE_N*LDF2 + TILE_N*LDS1 + 1024) * 4)

__global__ void __launch_bounds__(256, 1)
node_kernel(const float* __restrict__ h, const float* __restrict__ coords,
            const float* __restrict__ Wn1, const float* __restrict__ bn1,
            const float* __restrict__ Wn2, const float* __restrict__ bn2,
            float* __restrict__ out)
{
    extern __shared__ float sm[];
    float* sf2 = sm;                          // 128 x 260 (K=256 used)
    float* s1  = sf2 + TILE_N * LDF2;         // 128 x 132
    float* sW  = s1 + TILE_N * LDS1;          // 8 x 128

    const int tid = threadIdx.x;
    const int n0  = blockIdx.x * TILE_N;

    // load [h | h_agg] (zero-pad past N)
    for (int idx = tid; idx < TILE_N * 64; idx += 256) {
        const int r = idx >> 6, c = idx & 63;
        const int n = n0 + r;
        float4 v = make_float4(0.f, 0.f, 0.f, 0.f);
        if (n < N_NODES) {
            v = (c < 32) ? ((const float4*)h)[(size_t)n * 32 + c]
                         : ((const float4*)g_hagg)[(size_t)n * 32 + (c - 32)];
        }
        ((float4*)(sf2 + r * LDF2))[c] = v;
    }

    float acc[8][8];
    gemm128(sf2, LDF2, Wn1, 2 * H, 2 * H, sW, acc);
    silu_store(acc, bn1, s1);
    gemm128(s1, LDS1, Wn2, H, H, sW, acc);

    const int tx = tid & 15;
    const int ty = tid >> 4;
#pragma unroll
    for (int j = 0; j < 8; ++j) {
        const int c = tx * 8 + j;
        const float bb = bn2[c];
#pragma unroll
        for (int i = 0; i < 8; ++i) {
            const int n = n0 + ty * 8 + i;
            if (n < N_NODES)
                out[(size_t)n * H + c] = h[(size_t)n * H + c] + acc[i][j] + bb;
        }
    }

    if (tid < TILE_N) {
        const int n = n0 + tid;
        if (n < N_NODES) {
            const size_t base = (size_t)N_NODES * H;
            out[base + n * 3 + 0] = coords[n * 3 + 0] + g_xagg[n * 3 + 0];
            out[base + n * 3 + 1] = coords[n * 3 + 1] + g_xagg[n * 3 + 1];
            out[base + n * 3 + 2] = coords[n * 3 + 2] + g_xagg[n * 3 + 2];
        }
    }
}

// -------------------------------------------------------------------------
__global__ void zero_kernel()
{
    const int total = N_NODES * H + N_NODES * DIM;
    for (int i = blockIdx.x * blockDim.x + threadIdx.x; i < total;
         i += gridDim.x * blockDim.x) {
        if (i < N_NODES * H) g_hagg[i] = 0.f;
        else                 g_xagg[i - N_NODES * H] = 0.f;
    }
}

extern "C" void kernel_launch(void* const* d_in, const int* in_sizes, int n_in,
                              void* d_out, int out_size)
{
    const float* h      = (const float*)d_in[0];
    const float* coords = (const float*)d_in[1];
    const float* a      = (const float*)d_in[2];
    const int*   src    = (const int*)d_in[3];
    const int*   dst    = (const int*)d_in[4];
    const float* We1 = (const float*)d_in[5];
    const float* be1 = (const float*)d_in[6];
    const float* We2 = (const float*)d_in[7];
    const float* be2 = (const float*)d_in[8];
    const float* Wa  = (const float*)d_in[9];
    const float* ba  = (const float*)d_in[10];
    const float* Wn1 = (const float*)d_in[11];
    const float* bn1 = (const float*)d_in[12];
    const float* Wn2 = (const float*)d_in[13];
    const float* bn2 = (const float*)d_in[14];
    const float* Wc1 = (const float*)d_in[15];
    const float* bc1 = (const float*)d_in[16];
    const float* Wc2 = (const float*)d_in[17];
    const float* bc2 = (const float*)d_in[18];
    const float* Wc3 = (const float*)d_in[19];
    float* out = (float*)d_out;

    cudaFuncSetAttribute(edge_kernel, cudaFuncAttributeMaxDynamicSharedMemorySize, EDGE_SMEM);
    cudaFuncSetAttribute(node_kernel, cudaFuncAttributeMaxDynamicSharedMemorySize, NODE_SMEM);

    zero_kernel<<<512, 256>>>();
    edge_kernel<<<E_EDGES / TILE_E, 256, EDGE_SMEM>>>(
        h, coords, a, src, dst,
        We1, be1, We2, be2, Wa, ba, Wc1, bc1, Wc2, bc2, Wc3);
    node_kernel<<<(N_NODES + TILE_N - 1) / TILE_N, 256, NODE_SMEM>>>(
        h, coords, Wn1, bn1, Wn2, bn2, out);
}

// round 3
// speedup vs baseline: 3.2894x; 3.2894x over previous
#include <cuda_runtime.h>
#include <cuda_fp16.h>
#include <cstdint>
#include <math.h>

#define N_NODES 50000
#define E_EDGES 800000
#define H 128
#define MF 276

// ---------------------------------------------------------------------------
// Scratch (no cudaMalloc allowed)
// ---------------------------------------------------------------------------
__device__ float  g_hagg[N_NODES * H];
__device__ float  g_xagg[N_NODES * 3];
__device__ __half g_W1e[288 * 136];   // We1 fp16, rows k (zero-pad 276..287), cols n (pad 128..135)
__device__ __half g_W1c[288 * 136];   // Wc1 fp16
__device__ __half g_We2[128 * 136];
__device__ __half g_Wc2[128 * 136];
__device__ __half g_Wn1[256 * 136];
__device__ __half g_Wn2[128 * 136];

__device__ __forceinline__ uint32_t smem_u32(const void* p) {
    uint32_t a;
    asm("{ .reg .u64 t; cvta.to.shared.u64 t, %1; cvt.u32.u64 %0, t; }"
        : "=r"(a) : "l"(p));
    return a;
}
__device__ __forceinline__ float silu_f(float v) { return v / (1.f + __expf(-v)); }

__device__ __forceinline__ void red_add_v4(float* p, float a, float b, float c, float d) {
    asm volatile("red.global.add.v4.f32 [%0], {%1,%2,%3,%4};"
        :: "l"(p), "f"(a), "f"(b), "f"(c), "f"(d) : "memory");
}

// ---------------------------------------------------------------------------
// Warp-level fp16 GEMM building block.
// CTA: 256 threads = 8 warps in 4(M) x 2(N) grid; C tile 128x128.
// Each warp: 32 rows x 64 cols = 2 mtiles x 8 ntiles of m16n8, acc[2][8][4].
// A: row-major fp16 smem, stride aStride halves (stride%32words in {4,20}).
// B: row-major fp16 smem [K x 136].
// ---------------------------------------------------------------------------
__device__ __forceinline__ void zero_acc(float (&acc)[2][8][4]) {
#pragma unroll
    for (int mt = 0; mt < 2; ++mt)
#pragma unroll
        for (int nt = 0; nt < 8; ++nt)
#pragma unroll
            for (int i = 0; i < 4; ++i) acc[mt][nt][i] = 0.f;
}

__device__ __forceinline__ void gemm_frag(uint32_t aBase, int aStride, int aK0,
                                          uint32_t bBase, int ksteps,
                                          float (&acc)[2][8][4])
{
    const int lane = threadIdx.x & 31;
    const int wid  = threadIdx.x >> 5;
    const int wm   = wid & 3;
    const int wn   = wid >> 2;
    const int arow = wm * 32 + (lane & 15);
    const int acoff = (lane & 16) ? 8 : 0;
    const int brow = lane & 15;
    const int bcol = wn * 64 + ((lane & 16) ? 8 : 0);

    for (int ks = 0; ks < ksteps; ++ks) {
        const int kA = aK0 + ks * 16;
        const int kB = ks * 16;
        uint32_t a[2][4];
#pragma unroll
        for (int mt = 0; mt < 2; ++mt) {
            uint32_t ad = aBase + (uint32_t)(((arow + mt * 16) * aStride + kA + acoff) * 2);
            asm volatile("ldmatrix.sync.aligned.m8n8.x4.shared.b16 {%0,%1,%2,%3}, [%4];"
                : "=r"(a[mt][0]), "=r"(a[mt][1]), "=r"(a[mt][2]), "=r"(a[mt][3]) : "r"(ad));
        }
        uint32_t b[8][2];
#pragma unroll
        for (int nt2 = 0; nt2 < 4; ++nt2) {
            uint32_t bd = bBase + (uint32_t)(((kB + brow) * 136 + bcol + nt2 * 16) * 2);
            asm volatile("ldmatrix.sync.aligned.m8n8.x4.trans.shared.b16 {%0,%1,%2,%3}, [%4];"
                : "=r"(b[2 * nt2][0]), "=r"(b[2 * nt2][1]),
                  "=r"(b[2 * nt2 + 1][0]), "=r"(b[2 * nt2 + 1][1]) : "r"(bd));
        }
#pragma unroll
        for (int mt = 0; mt < 2; ++mt)
#pragma unroll
            for (int nt = 0; nt < 8; ++nt)
                asm volatile("mma.sync.aligned.m16n8k16.row.col.f32.f16.f16.f32 "
                    "{%0,%1,%2,%3}, {%4,%5,%6,%7}, {%8,%9}, {%0,%1,%2,%3};"
                    : "+f"(acc[mt][nt][0]), "+f"(acc[mt][nt][1]),
                      "+f"(acc[mt][nt][2]), "+f"(acc[mt][nt][3])
                    : "r"(a[mt][0]), "r"(a[mt][1]), "r"(a[mt][2]), "r"(a[mt][3]),
                      "r"(b[nt][0]), "r"(b[nt][1]));
    }
}

// register-staged global->smem copy (<= 9*256 float4)
__device__ __forceinline__ void load9(const float4* __restrict__ src, int cnt4, float4 (&rw)[9]) {
#pragma unroll
    for (int i = 0; i < 9; ++i) {
        int idx = threadIdx.x + i * 256;
        if (idx < cnt4) rw[i] = src[idx];
    }
}
__device__ __forceinline__ void store9(float4* dst, int cnt4, const float4 (&rw)[9]) {
#pragma unroll
    for (int i = 0; i < 9; ++i) {
        int idx = threadIdx.x + i * 256;
        if (idx < cnt4) dst[idx] = rw[i];
    }
}

// bias + silu from accumulators into fp16 act buffer [128 x 136]
__device__ __forceinline__ void epi_act(const float (&acc)[2][8][4],
                                        const float* __restrict__ sb, __half* act)
{
    const int lane = threadIdx.x & 31;
    const int wid  = threadIdx.x >> 5;
    const int wm = wid & 3, wn = wid >> 2;
#pragma unroll
    for (int mt = 0; mt < 2; ++mt)
#pragma unroll
        for (int nt = 0; nt < 8; ++nt) {
            const int row = wm * 32 + mt * 16 + (lane >> 2);
            const int col = wn * 64 + nt * 8 + (lane & 3) * 2;
            const float b0 = sb[col], b1 = sb[col + 1];
            *(half2*)(act + row * 136 + col) =
                __floats2half2_rn(silu_f(acc[mt][nt][0] + b0), silu_f(acc[mt][nt][1] + b1));
            *(half2*)(act + (row + 8) * 136 + col) =
                __floats2half2_rn(silu_f(acc[mt][nt][2] + b0), silu_f(acc[mt][nt][3] + b1));
        }
}

// ---------------------------------------------------------------------------
// prep: weights -> fp16 padded [K x 136]
// ---------------------------------------------------------------------------
__global__ void prep_kernel(const float* __restrict__ We1, const float* __restrict__ Wc1,
                            const float* __restrict__ We2, const float* __restrict__ Wc2,
                            const float* __restrict__ Wn1, const float* __restrict__ Wn2)
{
    const int stride = gridDim.x * blockDim.x;
    const __half hz = __float2half_rn(0.f);
    for (int i = blockIdx.x * blockDim.x + threadIdx.x; i < 288 * 136; i += stride) {
        int k = i / 136, n = i % 136;
        bool ok = (k < MF) && (n < 128);
        g_W1e[i] = ok ? __float2half_rn(We1[k * 128 + n]) : hz;
        g_W1c[i] = ok ? __float2half_rn(Wc1[k * 128 + n]) : hz;
    }
    for (int i = blockIdx.x * blockDim.x + threadIdx.x; i < 256 * 136; i += stride) {
        int k = i / 136, n = i % 136;
        g_Wn1[i] = (n < 128) ? __float2half_rn(Wn1[k * 128 + n]) : hz;
    }
    for (int i = blockIdx.x * blockDim.x + threadIdx.x; i < 128 * 136; i += stride) {
        int k = i / 136, n = i % 136;
        bool ok = (n < 128);
        g_We2[i] = ok ? __float2half_rn(We2[k * 128 + n]) : hz;
        g_Wc2[i] = ok ? __float2half_rn(Wc2[k * 128 + n]) : hz;
        g_Wn2[i] = ok ? __float2half_rn(Wn2[k * 128 + n]) : hz;
    }
}

__global__ void zero_kernel()
{
    const int total = N_NODES * H + N_NODES * 3;
    for (int i = blockIdx.x * blockDim.x + threadIdx.x; i < total;
         i += gridDim.x * blockDim.x) {
        if (i < N_NODES * H) g_hagg[i] = 0.f;
        else                 g_xagg[i - N_NODES * H] = 0.f;
    }
}

// ---------------------------------------------------------------------------
// Edge kernel: 1 CTA = 128 edges, 256 threads
// smem: f[128x296]h2 | Wstage 2x34816 | act[128x136]h2 | bias | satt | diff | dst | src
// ---------------------------------------------------------------------------
#define OF_F    0
#define OF_WS   75776
#define OF_ACT  145408
#define OF_BIAS 180224
#define OF_SATT 183296
#define OF_DIFF 183808
#define OF_DST  185856
#define OF_SRC  186368
#define EDGE_SMEM 186880

__global__ void __launch_bounds__(256, 1)
edge_kernel(const float* __restrict__ hmat, const float* __restrict__ coords,
            const float* __restrict__ amat,
            const int* __restrict__ src, const int* __restrict__ dst,
            const float* __restrict__ be1, const float* __restrict__ be2,
            const float* __restrict__ Wa,  const float* __restrict__ ba,
            const float* __restrict__ bc1, const float* __restrict__ bc2,
            const float* __restrict__ Wc3)
{
    extern __shared__ __align__(16) char sm[];
    __half* fA  = (__half*)(sm + OF_F);      // stride 296 halves
    __half* ws0 = (__half*)(sm + OF_WS);
    __half* ws1 = (__half*)(sm + OF_WS + 34816);
    __half* act = (__half*)(sm + OF_ACT);    // stride 136 halves
    float* sbe1 = (float*)(sm + OF_BIAS);
    float* sbc1 = sbe1 + 128;
    float* sbe2 = sbc1 + 128;
    float* sbc2 = sbe2 + 128;
    float* sWa  = sbc2 + 128;
    float* sWc3 = sWa + 128;
    float* satt = (float*)(sm + OF_SATT);
    float* sdiff = (float*)(sm + OF_DIFF);
    int* sdst = (int*)(sm + OF_DST);
    int* ssrc = (int*)(sm + OF_SRC);

    const uint32_t fU   = smem_u32(fA);
    const uint32_t ws0U = smem_u32(ws0);
    const uint32_t ws1U = smem_u32(ws1);
    const uint32_t actU = smem_u32(act);

    const int tid = threadIdx.x;
    const int e0  = blockIdx.x * 128;
    const float ba0 = ba[0];

    if (tid < 128) {
        sbe1[tid] = be1[tid]; sbc1[tid] = bc1[tid];
        sbe2[tid] = be2[tid]; sbc2[tid] = bc2[tid];
        sWa[tid]  = Wa[tid];  sWc3[tid] = Wc3[tid];
        const int e = e0 + tid;
        const int s_ = src[e], d_ = dst[e];
        ssrc[tid] = s_; sdst[tid] = d_;
        float dx = coords[s_ * 3 + 0] - coords[d_ * 3 + 0];
        float dy = coords[s_ * 3 + 1] - coords[d_ * 3 + 1];
        float dz = coords[s_ * 3 + 2] - coords[d_ * 3 + 2];
        float r  = sqrtf(dx * dx + dy * dy + dz * dz);
        sdiff[4 * tid + 0] = dx; sdiff[4 * tid + 1] = dy;
        sdiff[4 * tid + 2] = dz; sdiff[4 * tid + 3] = r;
        __half* fr = fA + tid * 296;
        *(half2*)(fr + 256) = __floats2half2_rn(r, fabsf(dx));
        *(half2*)(fr + 258) = __floats2half2_rn(fabsf(dy), fabsf(dz));
        const half2 z2 = __floats2half2_rn(0.f, 0.f);
#pragma unroll
        for (int c = 276; c < 288; c += 2) *(half2*)(fr + c) = z2;
    }
    __syncthreads();

    // gather h[src]|h[dst] (cols 0..255)
    for (int idx = tid; idx < 128 * 64; idx += 256) {
        const int el = idx >> 6, c = idx & 63;
        const int node = (c < 32) ? ssrc[el] : sdst[el];
        const float4 v = ((const float4*)hmat)[(size_t)node * 32 + (c & 31)];
        __half* p = fA + el * 296 + 4 * c;
        *(half2*)(p)     = __floats2half2_rn(v.x, v.y);
        *(half2*)(p + 2) = __floats2half2_rn(v.z, v.w);
    }
    // gather a (cols 260..275)
    for (int idx = tid; idx < 128 * 4; idx += 256) {
        const int el = idx >> 2, j = idx & 3;
        const float4 v = ((const float4*)amat)[(size_t)(e0 + el) * 4 + j];
        __half* p = fA + el * 296 + 260 + 4 * j;
        *(half2*)(p)     = __floats2half2_rn(v.x, v.y);
        *(half2*)(p + 2) = __floats2half2_rn(v.z, v.w);
    }

    float acc[2][8][4];
    float4 rw[9];

    // ===================== edge-MLP chain =====================
    zero_acc(acc);
    load9((const float4*)g_W1e, 2176, rw);            store9((float4*)ws0, 2176, rw);
    __syncthreads();
    load9(((const float4*)g_W1e) + 2176, 2176, rw);
    gemm_frag(fU, 296, 0, ws0U, 8, acc);
    store9((float4*)ws1, 2176, rw);
    __syncthreads();
    load9(((const float4*)g_W1e) + 4352, 544, rw);
    gemm_frag(fU, 296, 128, ws1U, 8, acc);
    store9((float4*)ws0, 544, rw);
    __syncthreads();
    gemm_frag(fU, 296, 256, ws0U, 2, acc);
    __syncthreads();

    epi_act(acc, sbe1, act);
    load9((const float4*)g_We2, 2176, rw);            store9((float4*)ws0, 2176, rw);
    __syncthreads();

    zero_acc(acc);
    gemm_frag(actU, 136, 0, ws0U, 8, acc);
    __syncthreads();
    epi_act(acc, sbe2, act);
    __syncthreads();

    // att = sigmoid(mh . Wa + ba)
    if (tid < 128) {
        const half2* ar2 = (const half2*)(act + tid * 136);
        float dot = 0.f;
#pragma unroll 8
        for (int c2 = 0; c2 < 64; ++c2) {
            float2 m = __half22float2(ar2[c2]);
            dot = fmaf(m.x, sWa[2 * c2], dot);
            dot = fmaf(m.y, sWa[2 * c2 + 1], dot);
        }
        satt[tid] = 1.f / (1.f + __expf(-(dot + ba0)));
    }
    __syncthreads();

    // scatter msg_h = att * mh (red.v4)
    {
        const int row = tid >> 1;
        const int cb  = (tid & 1) * 64;
        const float att = satt[row];
        float* hp = g_hagg + (size_t)sdst[row] * 128 + cb;
        const half2* ar2 = (const half2*)(act + row * 136 + cb);
#pragma unroll
        for (int j = 0; j < 16; ++j) {
            float2 x0 = __half22float2(ar2[2 * j]);
            float2 x1 = __half22float2(ar2[2 * j + 1]);
            red_add_v4(hp + 4 * j, att * x0.x, att * x0.y, att * x1.x, att * x1.y);
        }
    }

    // ===================== coord-MLP chain =====================
    zero_acc(acc);
    load9((const float4*)g_W1c, 2176, rw);            store9((float4*)ws0, 2176, rw);
    __syncthreads();
    load9(((const float4*)g_W1c) + 2176, 2176, rw);
    gemm_frag(fU, 296, 0, ws0U, 8, acc);
    store9((float4*)ws1, 2176, rw);
    __syncthreads();
    load9(((const float4*)g_W1c) + 4352, 544, rw);
    gemm_frag(fU, 296, 128, ws1U, 8, acc);
    store9((float4*)ws0, 544, rw);
    __syncthreads();
    gemm_frag(fU, 296, 256, ws0U, 2, acc);
    __syncthreads();

    epi_act(acc, sbc1, act);
    load9((const float4*)g_Wc2, 2176, rw);            store9((float4*)ws0, 2176, rw);
    __syncthreads();

    zero_acc(acc);
    gemm_frag(actU, 136, 0, ws0U, 8, acc);
    __syncthreads();
    epi_act(acc, sbc2, act);
    __syncthreads();

    if (tid < 128) {
        const half2* ar2 = (const half2*)(act + tid * 136);
        float dot = 0.f;
#pragma unroll 8
        for (int c2 = 0; c2 < 64; ++c2) {
            float2 m = __half22float2(ar2[c2]);
            dot = fmaf(m.x, sWc3[2 * c2], dot);
            dot = fmaf(m.y, sWc3[2 * c2 + 1], dot);
        }
        const float dx = sdiff[4 * tid + 0], dy = sdiff[4 * tid + 1];
        const float dz = sdiff[4 * tid + 2], r  = sdiff[4 * tid + 3];
        const float g = dot / (r + 1.f);
        const int d_ = sdst[tid];
        atomicAdd(&g_xagg[d_ * 3 + 0], g * dx);
        atomicAdd(&g_xagg[d_ * 3 + 1], g * dy);
        atomicAdd(&g_xagg[d_ * 3 + 2], g * dz);
    }
}

// ---------------------------------------------------------------------------
// Node kernel: 1 CTA = 128 nodes, 256 threads, fp16 mma
// ---------------------------------------------------------------------------
#define NOF_A    0
#define NOF_WS   67584
#define NOF_ACT  137216
#define NOF_BIAS 172032
#define NODE_SMEM 173056

__global__ void __launch_bounds__(256, 1)
node_kernel(const float* __restrict__ hmat, const float* __restrict__ coords,
            const float* __restrict__ bn1, const float* __restrict__ bn2,
            float* __restrict__ out)
{
    extern __shared__ __align__(16) char sm[];
    __half* A   = (__half*)(sm + NOF_A);     // stride 264 halves
    __half* ws  = (__half*)(sm + NOF_WS);
    __half* act = (__half*)(sm + NOF_ACT);
    float* sbn1 = (float*)(sm + NOF_BIAS);
    float* sbn2 = sbn1 + 128;

    const uint32_t aU = smem_u32(A), wsU = smem_u32(ws), actU = smem_u32(act);
    const int tid = threadIdx.x;
    const int n0  = blockIdx.x * 128;

    if (tid < 128) { sbn1[tid] = bn1[tid]; sbn2[tid] = bn2[tid]; }

    for (int idx = tid; idx < 128 * 64; idx += 256) {
        const int r = idx >> 6, c = idx & 63;
        const int n = n0 + r;
        float4 v = make_float4(0.f, 0.f, 0.f, 0.f);
        if (n < N_NODES)
            v = (c < 32) ? ((const float4*)hmat)[(size_t)n * 32 + c]
                         : ((const float4*)g_hagg)[(size_t)n * 32 + (c - 32)];
        __half* p = A + r * 264 + 4 * c;
        *(half2*)(p)     = __floats2half2_rn(v.x, v.y);
        *(half2*)(p + 2) = __floats2half2_rn(v.z, v.w);
    }
    {
        const float4* s4 = (const float4*)g_Wn1;
        float4* d4 = (float4*)ws;
        for (int i = tid; i < 4352; i += 256) d4[i] = s4[i];
    }
    __syncthreads();

    float acc[2][8][4];
    zero_acc(acc);
    gemm_frag(aU, 264, 0, wsU, 16, acc);
    __syncthreads();
    epi_act(acc, sbn1, act);
    {
        const float4* s4 = (const float4*)g_Wn2;
        float4* d4 = (float4*)ws;
        for (int i = tid; i < 2176; i += 256) d4[i] = s4[i];
    }
    __syncthreads();
    zero_acc(acc);
    gemm_frag(actU, 136, 0, wsU, 8, acc);

    // h_out = h + (acc + bn2)
    const int lane = tid & 31;
    const int wid  = tid >> 5;
    const int wm = wid & 3, wn = wid >> 2;
#pragma unroll
    for (int mt = 0; mt < 2; ++mt)
#pragma unroll
        for (int nt = 0; nt < 8; ++nt) {
            const int row = wm * 32 + mt * 16 + (lane >> 2);
            const int col = wn * 64 + nt * 8 + (lane & 3) * 2;
            const float b0 = sbn2[col], b1 = sbn2[col + 1];
            int n = n0 + row;
            if (n < N_NODES) {
                float2 hv = *(const float2*)(hmat + (size_t)n * 128 + col);
                float2 o = make_float2(hv.x + acc[mt][nt][0] + b0,
                                       hv.y + acc[mt][nt][1] + b1);
                *(float2*)(out + (size_t)n * 128 + col) = o;
            }
            n = n0 + row + 8;
            if (n < N_NODES) {
                float2 hv = *(const float2*)(hmat + (size_t)n * 128 + col);
                float2 o = make_float2(hv.x + acc[mt][nt][2] + b0,
                                       hv.y + acc[mt][nt][3] + b1);
                *(float2*)(out + (size_t)n * 128 + col) = o;
            }
        }

    if (tid < 128) {
        const int n = n0 + tid;
        if (n < N_NODES) {
            const size_t base = (size_t)N_NODES * 128;
            out[base + n * 3 + 0] = coords[n * 3 + 0] + g_xagg[n * 3 + 0];
            out[base + n * 3 + 1] = coords[n * 3 + 1] + g_xagg[n * 3 + 1];
            out[base + n * 3 + 2] = coords[n * 3 + 2] + g_xagg[n * 3 + 2];
        }
    }
}

// ---------------------------------------------------------------------------
extern "C" void kernel_launch(void* const* d_in, const int* in_sizes, int n_in,
                              void* d_out, int out_size)
{
    const float* h      = (const float*)d_in[0];
    const float* coords = (const float*)d_in[1];
    const float* a      = (const float*)d_in[2];
    const int*   src    = (const int*)d_in[3];
    const int*   dst    = (const int*)d_in[4];
    const float* We1 = (const float*)d_in[5];
    const float* be1 = (const float*)d_in[6];
    const float* We2 = (const float*)d_in[7];
    const float* be2 = (const float*)d_in[8];
    const float* Wa  = (const float*)d_in[9];
    const float* ba  = (const float*)d_in[10];
    const float* Wn1 = (const float*)d_in[11];
    const float* bn1 = (const float*)d_in[12];
    const float* Wn2 = (const float*)d_in[13];
    const float* bn2 = (const float*)d_in[14];
    const float* Wc1 = (const float*)d_in[15];
    const float* bc1 = (const float*)d_in[16];
    const float* Wc2 = (const float*)d_in[17];
    const float* bc2 = (const float*)d_in[18];
    const float* Wc3 = (const float*)d_in[19];
    float* out = (float*)d_out;

    cudaFuncSetAttribute(edge_kernel, cudaFuncAttributeMaxDynamicSharedMemorySize, EDGE_SMEM);
    cudaFuncSetAttribute(node_kernel, cudaFuncAttributeMaxDynamicSharedMemorySize, NODE_SMEM);

    zero_kernel<<<512, 256>>>();
    prep_kernel<<<256, 256>>>(We1, Wc1, We2, Wc2, Wn1, Wn2);
    edge_kernel<<<E_EDGES / 128, 256, EDGE_SMEM>>>(
        h, coords, a, src, dst, be1, be2, Wa, ba, bc1, bc2, Wc3);
    node_kernel<<<(N_NODES + 127) / 128, 256, NODE_SMEM>>>(
        h, coords, bn1, bn2, out);
}